// round 13
// baseline (speedup 1.0000x reference)
#include <cuda_runtime.h>
#include <cuda_bf16.h>
#include <stdint.h>

#define BATCH 4
#define NQ    2048
#define SEQ   2048
#define NH    16
#define DKH   64
#define DM    1024
#define BH    (BATCH * NH)
#define QK_SCALE 0.125f
#define CSLOG2E (0.125f * 1.44269504f)   // QK_SCALE * log2(e)

// ---------------- persistent scratch (allocation-free rule) -----------------
__device__ __nv_bfloat16 g_Kh[(size_t)BH * SEQ * DKH];
__device__ __nv_bfloat16 g_Kl[(size_t)BH * SEQ * DKH];
__device__ __nv_bfloat16 g_Vh[(size_t)BH * DKH * SEQ];   // transposed [b,h,d,s]
__device__ __nv_bfloat16 g_Vl[(size_t)BH * DKH * SEQ];
__device__ __nv_bfloat16 g_Ch[(size_t)BATCH * NQ * DM];  // ctx hi plane
__device__ __nv_bfloat16 g_Cl[(size_t)BATCH * NQ * DM];  // ctx lo plane
__device__ __nv_bfloat16 g_Wh[(size_t)DM * DM];
__device__ __nv_bfloat16 g_Wl[(size_t)DM * DM];

// ---------------------------------------------------------------------------
__device__ __forceinline__ void mma_bf16(float d[4], const uint32_t a[4],
                                         uint32_t b0, uint32_t b1) {
    asm volatile(
        "mma.sync.aligned.m16n8k16.row.col.f32.bf16.bf16.f32 "
        "{%0,%1,%2,%3}, {%4,%5,%6,%7}, {%8,%9}, {%0,%1,%2,%3};\n"
        : "+f"(d[0]), "+f"(d[1]), "+f"(d[2]), "+f"(d[3])
        : "r"(a[0]), "r"(a[1]), "r"(a[2]), "r"(a[3]), "r"(b0), "r"(b1));
}

__device__ __forceinline__ void ldsm_x4(uint32_t& r0, uint32_t& r1,
                                        uint32_t& r2, uint32_t& r3, uint32_t addr) {
    asm volatile("ldmatrix.sync.aligned.m8n8.x4.shared.b16 {%0,%1,%2,%3}, [%4];\n"
                 : "=r"(r0), "=r"(r1), "=r"(r2), "=r"(r3) : "r"(addr));
}

__device__ __forceinline__ float ex2f(float x) {
    float y;
    asm("ex2.approx.f32 %0, %1;" : "=f"(y) : "f"(x));
    return y;
}

__device__ __forceinline__ void split_pack(float x, float y, uint32_t& hi, uint32_t& lo) {
    __nv_bfloat16 xh = __float2bfloat16_rn(x);
    __nv_bfloat16 yh = __float2bfloat16_rn(y);
    __nv_bfloat16 xl = __float2bfloat16_rn(x - __bfloat162float(xh));
    __nv_bfloat16 yl = __float2bfloat16_rn(y - __bfloat162float(yh));
    __nv_bfloat162 h2 = __halves2bfloat162(xh, yh);
    __nv_bfloat162 l2 = __halves2bfloat162(xl, yl);
    hi = *reinterpret_cast<uint32_t*>(&h2);
    lo = *reinterpret_cast<uint32_t*>(&l2);
}

__device__ __forceinline__ void cp16(uint32_t dst, const void* src) {
    asm volatile("cp.async.cg.shared.global [%0], [%1], 16;\n" :: "r"(dst), "l"(src));
}
#define CP_COMMIT()  asm volatile("cp.async.commit_group;\n")
#define CP_WAIT(n)   asm volatile("cp.async.wait_group %0;\n" :: "n"(n))

// ---------------------------------------------------------------------------
// Prepass: K -> bf16 hi/lo [bh][s][d]; V -> bf16 hi/lo transposed [bh][d][s].
// ---------------------------------------------------------------------------
__global__ void __launch_bounds__(256) convert_kv(const float* __restrict__ K,
                                                  const float* __restrict__ V) {
    __shared__ float sV[64][65];
    const int st = blockIdx.x, h = blockIdx.y, b = blockIdx.z;
    const int tid = threadIdx.x;
    const int bh = b * NH + h;
    const size_t kdst_base = (size_t)bh * SEQ * DKH + (size_t)st * 64 * DKH;

    #pragma unroll
    for (int it = 0; it < 4; it++) {
        int idx = it * 256 + tid;
        int r = idx >> 4, c4 = (idx & 15) << 2;
        size_t src = ((size_t)(b * SEQ + st * 64 + r)) * DM + h * DKH + c4;
        float4 kv = *reinterpret_cast<const float4*>(K + src);
        float4 vv = *reinterpret_cast<const float4*>(V + src);
        uint32_t h0, l0, h1, l1;
        split_pack(kv.x, kv.y, h0, l0);
        split_pack(kv.z, kv.w, h1, l1);
        size_t d = kdst_base + (size_t)r * DKH + c4;
        *reinterpret_cast<uint2*>(g_Kh + d) = make_uint2(h0, h1);
        *reinterpret_cast<uint2*>(g_Kl + d) = make_uint2(l0, l1);
        sV[r][c4] = vv.x; sV[r][c4 + 1] = vv.y; sV[r][c4 + 2] = vv.z; sV[r][c4 + 3] = vv.w;
    }
    __syncthreads();
    #pragma unroll
    for (int it = 0; it < 4; it++) {
        int idx = it * 256 + tid;
        int d = idx >> 4, s4 = (idx & 15) << 2;
        float x0 = sV[s4][d], x1 = sV[s4 + 1][d], x2 = sV[s4 + 2][d], x3 = sV[s4 + 3][d];
        uint32_t h0, l0, h1, l1;
        split_pack(x0, x1, h0, l0);
        split_pack(x2, x3, h1, l1);
        size_t dst = ((size_t)bh * DKH + d) * SEQ + st * 64 + s4;
        *reinterpret_cast<uint2*>(g_Vh + dst) = make_uint2(h0, h1);
        *reinterpret_cast<uint2*>(g_Vl + dst) = make_uint2(l0, l1);
    }
}

__global__ void __launch_bounds__(256) convert_w(const float* __restrict__ Wo) {
    int idx = blockIdx.x * 256 + threadIdx.x;
    size_t e = (size_t)idx * 4;
    float4 w = *reinterpret_cast<const float4*>(Wo + e);
    uint32_t h0, l0, h1, l1;
    split_pack(w.x, w.y, h0, l0);
    split_pack(w.z, w.w, h1, l1);
    *reinterpret_cast<uint2*>(g_Wh + e) = make_uint2(h0, h1);
    *reinterpret_cast<uint2*>(g_Wl + e) = make_uint2(l0, l1);
}

// ---------------------------------------------------------------------------
// Attention: CTA = 128 queries x one head, 256 threads.
// 3-stage cp.async pipeline, ONE __syncthreads per tile, softmax interleaved
// with PV per 16-column chunk so scalar work hides under tensor work.
// ---------------------------------------------------------------------------
#define LDA 72
#define PLANE (64 * LDA)
#define STAGE (4 * PLANE)              // Kh,Kl,Vh,Vl (elems)
#define NSTG  3
#define ATTN_SMEM (NSTG * STAGE * 2)   // 110592 B

__global__ void __launch_bounds__(256, 2) attn_kernel(const float* __restrict__ Qg,
                                                      const float* __restrict__ AWg) {
    extern __shared__ __nv_bfloat16 sm[];
    const uint32_t smbase = (uint32_t)__cvta_generic_to_shared(sm);

    const int qt = blockIdx.x, h = blockIdx.y, b = blockIdx.z;
    const int tid = threadIdx.x;
    const int warp = tid >> 5, lane = tid & 31;
    const int g = lane >> 2, tq = lane & 3;
    const int q0 = qt * 128;
    const int bh = b * NH + h;

    // ldmatrix per-thread row offset for B-fragments ([n][k] tiles)
    const int browoff = (((lane >> 4) << 3) + (lane & 7)) * LDA + (((lane >> 3) & 1) << 3);

    const size_t kplane = (size_t)bh * SEQ * DKH;
    const __nv_bfloat16* gKh = g_Kh + kplane;
    const __nv_bfloat16* gKl = g_Kl + kplane;
    const __nv_bfloat16* gVh = g_Vh + kplane;
    const __nv_bfloat16* gVl = g_Vl + kplane;

    auto stage_load = [&](int st, int sb) {
        const size_t ko = (size_t)st * 64 * DKH;
        const int vo = st * 64;
        #pragma unroll
        for (int i = 0; i < 8; i++) {
            int id = tid + i * 256;
            int plane = id >> 9, rem = id & 511;
            int r = rem >> 3, c = rem & 7;
            const __nv_bfloat16* src;
            if (plane == 0)      src = gKh + ko + (size_t)r * DKH + c * 8;
            else if (plane == 1) src = gKl + ko + (size_t)r * DKH + c * 8;
            else if (plane == 2) src = gVh + (size_t)r * SEQ + vo + c * 8;
            else                 src = gVl + (size_t)r * SEQ + vo + c * 8;
            cp16(smbase + (sb * STAGE + plane * PLANE + r * LDA + c * 8) * 2, src);
        }
        CP_COMMIT();
    };

    stage_load(0, 0);
    stage_load(1, 1);

    // ---- Q fragments straight from gmem (one-time) ----
    uint32_t qah[4][4], qal[4][4];
    {
        const float* Q0 = Qg + ((size_t)b * NQ + q0 + warp * 16 + g) * DM + h * DKH;
        const float* Q1 = Q0 + (size_t)8 * DM;
        #pragma unroll
        for (int kt = 0; kt < 4; kt++) {
            int c0 = kt * 16 + tq * 2;
            float2 x0 = *reinterpret_cast<const float2*>(Q0 + c0);
            float2 x1 = *reinterpret_cast<const float2*>(Q1 + c0);
            float2 x2 = *reinterpret_cast<const float2*>(Q0 + c0 + 8);
            float2 x3 = *reinterpret_cast<const float2*>(Q1 + c0 + 8);
            split_pack(x0.x, x0.y, qah[kt][0], qal[kt][0]);
            split_pack(x1.x, x1.y, qah[kt][1], qal[kt][1]);
            split_pack(x2.x, x2.y, qah[kt][2], qal[kt][2]);
            split_pack(x3.x, x3.y, qah[kt][3], qal[kt][3]);
        }
    }

    const float* Wr0 = AWg + ((size_t)bh * NQ + q0 + warp * 16 + g) * SEQ + tq * 2;
    const float* Wr1 = Wr0 + (size_t)8 * SEQ;

    float acc[8][4];
    #pragma unroll
    for (int j = 0; j < 8; j++) { acc[j][0] = acc[j][1] = acc[j][2] = acc[j][3] = 0.f; }
    float L0 = 0.f, L1 = 0.f;

    for (int st = 0; st < SEQ / 64; st++) {
        // wait for tile st's stage, then (after barrier) prefetch st+2
        if (st < SEQ / 64 - 1) { CP_WAIT(1); } else { CP_WAIT(0); }
        __syncthreads();
        if (st + 2 < SEQ / 64) stage_load(st + 2, (st + 2) % NSTG);

        const int buf = st % NSTG;
        const uint32_t sKh = smbase + (buf * STAGE) * 2;
        const uint32_t sVh = sKh + (2 * PLANE) * 2;

        // prefetch W chunk 0 (latency hidden under QK MMAs)
        float2 wbuf[2][4];
        {
            const float* Wc0 = Wr0 + st * 64;
            const float* Wc1 = Wr1 + st * 64;
            wbuf[0][0] = __ldg(reinterpret_cast<const float2*>(Wc0));
            wbuf[0][1] = __ldg(reinterpret_cast<const float2*>(Wc0 + 8));
            wbuf[0][2] = __ldg(reinterpret_cast<const float2*>(Wc1));
            wbuf[0][3] = __ldg(reinterpret_cast<const float2*>(Wc1 + 8));
        }

        // ---- QK^T (3-pass hi/lo split), ldmatrix fragments ----
        float sc[8][4];
        #pragma unroll
        for (int j = 0; j < 8; j++) { sc[j][0] = sc[j][1] = sc[j][2] = sc[j][3] = 0.f; }
        #pragma unroll
        for (int kt = 0; kt < 4; kt++) {
            #pragma unroll
            for (int jp = 0; jp < 4; jp++) {
                uint32_t a = sKh + (jp * 16 * LDA + browoff + kt * 16) * 2;
                uint32_t h0, h1, h2, h3, l0, l1, l2, l3;
                ldsm_x4(h0, h1, h2, h3, a);
                ldsm_x4(l0, l1, l2, l3, a + PLANE * 2);
                mma_bf16(sc[2 * jp],     qah[kt], h0, h1);
                mma_bf16(sc[2 * jp],     qah[kt], l0, l1);
                mma_bf16(sc[2 * jp],     qal[kt], h0, h1);
                mma_bf16(sc[2 * jp + 1], qah[kt], h2, h3);
                mma_bf16(sc[2 * jp + 1], qah[kt], l2, l3);
                mma_bf16(sc[2 * jp + 1], qal[kt], h2, h3);
            }
        }

        // ---- interleaved softmax + PV, 16-column chunks ----
        float rs0 = 0.f, rs1 = 0.f;
        #pragma unroll
        for (int kt = 0; kt < 4; kt++) {
            // prefetch W chunk kt+1 (hidden under this chunk's PV MMAs)
            if (kt < 3) {
                const float* Wc0 = Wr0 + st * 64 + (2 * (kt + 1)) * 8;
                const float* Wc1 = Wr1 + st * 64 + (2 * (kt + 1)) * 8;
                wbuf[(kt + 1) & 1][0] = __ldg(reinterpret_cast<const float2*>(Wc0));
                wbuf[(kt + 1) & 1][1] = __ldg(reinterpret_cast<const float2*>(Wc0 + 8));
                wbuf[(kt + 1) & 1][2] = __ldg(reinterpret_cast<const float2*>(Wc1));
                wbuf[(kt + 1) & 1][3] = __ldg(reinterpret_cast<const float2*>(Wc1 + 8));
            }

            const int j0 = 2 * kt, j1 = j0 + 1;
            const float2 wa = wbuf[kt & 1][0], wb = wbuf[kt & 1][1];
            const float2 wc = wbuf[kt & 1][2], wd = wbuf[kt & 1][3];
            float p00 = ex2f(sc[j0][0] * CSLOG2E * wa.x);
            float p01 = ex2f(sc[j0][1] * CSLOG2E * wa.y);
            float p10 = ex2f(sc[j0][2] * CSLOG2E * wc.x);
            float p11 = ex2f(sc[j0][3] * CSLOG2E * wc.y);
            float q00 = ex2f(sc[j1][0] * CSLOG2E * wb.x);
            float q01 = ex2f(sc[j1][1] * CSLOG2E * wb.y);
            float q10 = ex2f(sc[j1][2] * CSLOG2E * wd.x);
            float q11 = ex2f(sc[j1][3] * CSLOG2E * wd.y);
            rs0 += p00 + p01 + q00 + q01;
            rs1 += p10 + p11 + q10 + q11;

            uint32_t pah[4], pal[4];
            split_pack(p00, p01, pah[0], pal[0]);
            split_pack(p10, p11, pah[1], pal[1]);
            split_pack(q00, q01, pah[2], pal[2]);
            split_pack(q10, q11, pah[3], pal[3]);

            #pragma unroll
            for (int jp = 0; jp < 4; jp++) {
                uint32_t a = sVh + (jp * 16 * LDA + browoff + kt * 16) * 2;
                uint32_t h0, h1, h2, h3, l0, l1, l2, l3;
                ldsm_x4(h0, h1, h2, h3, a);
                ldsm_x4(l0, l1, l2, l3, a + PLANE * 2);
                mma_bf16(acc[2 * jp],     pah, h0, h1);
                mma_bf16(acc[2 * jp],     pah, l0, l1);
                mma_bf16(acc[2 * jp],     pal, h0, h1);
                mma_bf16(acc[2 * jp + 1], pah, h2, h3);
                mma_bf16(acc[2 * jp + 1], pah, l2, l3);
                mma_bf16(acc[2 * jp + 1], pal, h2, h3);
            }
        }

        rs0 += __shfl_xor_sync(0xffffffffu, rs0, 1);
        rs0 += __shfl_xor_sync(0xffffffffu, rs0, 2);
        rs1 += __shfl_xor_sync(0xffffffffu, rs1, 1);
        rs1 += __shfl_xor_sync(0xffffffffu, rs1, 2);
        L0 += rs0;
        L1 += rs1;
    }

    // ---- epilogue: normalize, split to bf16 hi/lo ctx planes ----
    float inv0 = 1.f / L0, inv1 = 1.f / L1;
    size_t C0 = ((size_t)b * NQ + q0 + warp * 16 + g) * DM + h * DKH;
    size_t C1 = C0 + (size_t)8 * DM;
    #pragma unroll
    for (int j = 0; j < 8; j++) {
        int c = j * 8 + tq * 2;
        uint32_t h0, l0, h1, l1;
        split_pack(acc[j][0] * inv0, acc[j][1] * inv0, h0, l0);
        split_pack(acc[j][2] * inv1, acc[j][3] * inv1, h1, l1);
        *reinterpret_cast<uint32_t*>(g_Ch + C0 + c) = h0;
        *reinterpret_cast<uint32_t*>(g_Cl + C0 + c) = l0;
        *reinterpret_cast<uint32_t*>(g_Ch + C1 + c) = h1;
        *reinterpret_cast<uint32_t*>(g_Cl + C1 + c) = l1;
    }
}

// ---------------------------------------------------------------------------
// Projection: out = ctx @ W^T + b. 128m x 64n, k-chunk 32, 3-stage cp.async
// pipeline with ONE __syncthreads per iteration, ldmatrix fragments.
// ---------------------------------------------------------------------------
#define LDK 40
#define PA  (128 * LDK)
#define PB  (64 * LDK)
#define PSTAGE (2 * PA + 2 * PB)       // elems per stage
#define PNSTG 3
#define PROJ_SMEM (PNSTG * PSTAGE * 2) // 92160 B

__global__ void __launch_bounds__(256) proj_kernel(const float* __restrict__ bo,
                                                   float* __restrict__ out) {
    extern __shared__ __nv_bfloat16 sm[];
    const uint32_t smbase = (uint32_t)__cvta_generic_to_shared(sm);

    const int n0 = blockIdx.x * 64;
    const int m0 = blockIdx.y * 128;
    const int tid = threadIdx.x;
    const int warp = tid >> 5, lane = tid & 31;
    const int g = lane >> 2, tq = lane & 3;

    const int browoff = (((lane >> 4) << 3) + (lane & 7)) * LDK + (((lane >> 3) & 1) << 3);
    const int arowoff = ((((lane >> 3) & 1) << 3) + (lane & 7)) * LDK + ((lane >> 4) << 3);

    float acc[8][4];
    #pragma unroll
    for (int j = 0; j < 8; j++) { acc[j][0] = acc[j][1] = acc[j][2] = acc[j][3] = 0.f; }

    auto load_stage = [&](int kc, int buf) {
        const int k0 = kc * 32;
        #pragma unroll
        for (int i = 0; i < 6; i++) {
            int id = tid + i * 256;
            const __nv_bfloat16* src;
            uint32_t dst;
            if (id < 1024) {
                int plane = id >> 9, rem = id & 511;
                int r = rem >> 2, c = rem & 3;
                const __nv_bfloat16* gp = plane ? g_Cl : g_Ch;
                src = gp + (size_t)(m0 + r) * DM + k0 + c * 8;
                dst = smbase + (buf * PSTAGE + plane * PA + r * LDK + c * 8) * 2;
            } else {
                int id2 = id - 1024;
                int plane = id2 >> 8, rem = id2 & 255;
                int r = rem >> 2, c = rem & 3;
                const __nv_bfloat16* gp = plane ? g_Wl : g_Wh;
                src = gp + (size_t)(n0 + r) * DM + k0 + c * 8;
                dst = smbase + (buf * PSTAGE + 2 * PA + plane * PB + r * LDK + c * 8) * 2;
            }
            cp16(dst, src);
        }
        CP_COMMIT();
    };

    load_stage(0, 0);
    load_stage(1, 1);

    const int NK = DM / 32;
    for (int kc = 0; kc < NK; kc++) {
        if (kc < NK - 1) { CP_WAIT(1); } else { CP_WAIT(0); }
        __syncthreads();
        if (kc + 2 < NK) load_stage(kc + 2, (kc + 2) % PNSTG);

        const int buf = kc % PNSTG;
        const uint32_t sA = smbase + (buf * PSTAGE) * 2;
        const uint32_t sB = sA + (2 * PA) * 2;

        uint32_t ah[2][4], al[2][4];
        #pragma unroll
        for (int kt = 0; kt < 2; kt++) {
            uint32_t a = sA + (warp * 16 * LDK + arowoff + kt * 16) * 2;
            ldsm_x4(ah[kt][0], ah[kt][1], ah[kt][2], ah[kt][3], a);
            ldsm_x4(al[kt][0], al[kt][1], al[kt][2], al[kt][3], a + PA * 2);
        }
        #pragma unroll
        for (int kt = 0; kt < 2; kt++) {
            #pragma unroll
            for (int jp = 0; jp < 4; jp++) {
                uint32_t a = sB + (jp * 16 * LDK + browoff + kt * 16) * 2;
                uint32_t h0, h1, h2, h3, l0, l1, l2, l3;
                ldsm_x4(h0, h1, h2, h3, a);
                ldsm_x4(l0, l1, l2, l3, a + PB * 2);
                mma_bf16(acc[2 * jp],     ah[kt], h0, h1);
                mma_bf16(acc[2 * jp],     ah[kt], l0, l1);
                mma_bf16(acc[2 * jp],     al[kt], h0, h1);
                mma_bf16(acc[2 * jp + 1], ah[kt], h2, h3);
                mma_bf16(acc[2 * jp + 1], ah[kt], l2, l3);
                mma_bf16(acc[2 * jp + 1], al[kt], h2, h3);
            }
        }
    }

    int r0 = m0 + warp * 16 + g, r1 = r0 + 8;
    #pragma unroll
    for (int j = 0; j < 8; j++) {
        int c = n0 + j * 8 + tq * 2;
        float2 bb = *reinterpret_cast<const float2*>(bo + c);
        float2 o0 = make_float2(acc[j][0] + bb.x, acc[j][1] + bb.y);
        float2 o1 = make_float2(acc[j][2] + bb.x, acc[j][3] + bb.y);
        *reinterpret_cast<float2*>(out + (size_t)r0 * DM + c) = o0;
        *reinterpret_cast<float2*>(out + (size_t)r1 * DM + c) = o1;
    }
}

// ---------------------------------------------------------------------------
extern "C" void kernel_launch(void* const* d_in, const int* in_sizes, int n_in,
                              void* d_out, int out_size) {
    const float* Q  = (const float*)d_in[0];
    const float* K  = (const float*)d_in[1];
    const float* V  = (const float*)d_in[2];
    const float* AW = (const float*)d_in[3];
    const float* Wo = (const float*)d_in[4];
    const float* bo = (const float*)d_in[5];
    float* out = (float*)d_out;

    cudaFuncSetAttribute(attn_kernel, cudaFuncAttributeMaxDynamicSharedMemorySize, ATTN_SMEM);
    cudaFuncSetAttribute(proj_kernel, cudaFuncAttributeMaxDynamicSharedMemorySize, PROJ_SMEM);

    convert_kv<<<dim3(SEQ / 64, NH, BATCH), 256>>>(K, V);
    convert_w<<<DM * DM / 1024, 256>>>(Wo);
    attn_kernel<<<dim3(NQ / 128, NH, BATCH), 256, ATTN_SMEM>>>(Q, AW);
    proj_kernel<<<dim3(DM / 64, BATCH * NQ / 128), 256, PROJ_SMEM>>>(bo, out);
}

// round 14
// speedup vs baseline: 1.0025x; 1.0025x over previous
#include <cuda_runtime.h>
#include <cuda_bf16.h>
#include <stdint.h>

#define BATCH 4
#define NQ    2048
#define SEQ   2048
#define NH    16
#define DKH   64
#define DM    1024
#define BH    (BATCH * NH)
#define QK_SCALE 0.125f
#define CSLOG2E (0.125f * 1.44269504f)   // QK_SCALE * log2(e)

// ---------------- persistent scratch (allocation-free rule) -----------------
__device__ __nv_bfloat16 g_Kh[(size_t)BH * SEQ * DKH];
__device__ __nv_bfloat16 g_Kl[(size_t)BH * SEQ * DKH];
__device__ __nv_bfloat16 g_Vh[(size_t)BH * DKH * SEQ];   // transposed [b,h,d,s]
__device__ __nv_bfloat16 g_Vl[(size_t)BH * DKH * SEQ];
__device__ __nv_bfloat16 g_Ch[(size_t)BATCH * NQ * DM];  // ctx hi plane
__device__ __nv_bfloat16 g_Cl[(size_t)BATCH * NQ * DM];  // ctx lo plane
__device__ __nv_bfloat16 g_Wh[(size_t)DM * DM];
__device__ __nv_bfloat16 g_Wl[(size_t)DM * DM];

// ---------------------------------------------------------------------------
__device__ __forceinline__ void mma_bf16(float d[4], const uint32_t a[4],
                                         uint32_t b0, uint32_t b1) {
    asm volatile(
        "mma.sync.aligned.m16n8k16.row.col.f32.bf16.bf16.f32 "
        "{%0,%1,%2,%3}, {%4,%5,%6,%7}, {%8,%9}, {%0,%1,%2,%3};\n"
        : "+f"(d[0]), "+f"(d[1]), "+f"(d[2]), "+f"(d[3])
        : "r"(a[0]), "r"(a[1]), "r"(a[2]), "r"(a[3]), "r"(b0), "r"(b1));
}

__device__ __forceinline__ void ldsm_x4(uint32_t& r0, uint32_t& r1,
                                        uint32_t& r2, uint32_t& r3, uint32_t addr) {
    asm volatile("ldmatrix.sync.aligned.m8n8.x4.shared.b16 {%0,%1,%2,%3}, [%4];\n"
                 : "=r"(r0), "=r"(r1), "=r"(r2), "=r"(r3) : "r"(addr));
}

__device__ __forceinline__ float ex2f(float x) {
    float y;
    asm("ex2.approx.f32 %0, %1;" : "=f"(y) : "f"(x));
    return y;
}

__device__ __forceinline__ void split_pack(float x, float y, uint32_t& hi, uint32_t& lo) {
    __nv_bfloat16 xh = __float2bfloat16_rn(x);
    __nv_bfloat16 yh = __float2bfloat16_rn(y);
    __nv_bfloat16 xl = __float2bfloat16_rn(x - __bfloat162float(xh));
    __nv_bfloat16 yl = __float2bfloat16_rn(y - __bfloat162float(yh));
    __nv_bfloat162 h2 = __halves2bfloat162(xh, yh);
    __nv_bfloat162 l2 = __halves2bfloat162(xl, yl);
    hi = *reinterpret_cast<uint32_t*>(&h2);
    lo = *reinterpret_cast<uint32_t*>(&l2);
}

__device__ __forceinline__ void cp16(uint32_t dst, const void* src) {
    asm volatile("cp.async.cg.shared.global [%0], [%1], 16;\n" :: "r"(dst), "l"(src));
}
#define CP_COMMIT()  asm volatile("cp.async.commit_group;\n")
#define CP_WAIT(n)   asm volatile("cp.async.wait_group %0;\n" :: "n"(n))

// ---------------------------------------------------------------------------
// Prepass: K -> bf16 hi/lo [bh][s][d]; V -> bf16 hi/lo transposed [bh][d][s].
// ---------------------------------------------------------------------------
__global__ void __launch_bounds__(256) convert_kv(const float* __restrict__ K,
                                                  const float* __restrict__ V) {
    __shared__ float sV[64][65];
    const int st = blockIdx.x, h = blockIdx.y, b = blockIdx.z;
    const int tid = threadIdx.x;
    const int bh = b * NH + h;
    const size_t kdst_base = (size_t)bh * SEQ * DKH + (size_t)st * 64 * DKH;

    #pragma unroll
    for (int it = 0; it < 4; it++) {
        int idx = it * 256 + tid;
        int r = idx >> 4, c4 = (idx & 15) << 2;
        size_t src = ((size_t)(b * SEQ + st * 64 + r)) * DM + h * DKH + c4;
        float4 kv = *reinterpret_cast<const float4*>(K + src);
        float4 vv = *reinterpret_cast<const float4*>(V + src);
        uint32_t h0, l0, h1, l1;
        split_pack(kv.x, kv.y, h0, l0);
        split_pack(kv.z, kv.w, h1, l1);
        size_t d = kdst_base + (size_t)r * DKH + c4;
        *reinterpret_cast<uint2*>(g_Kh + d) = make_uint2(h0, h1);
        *reinterpret_cast<uint2*>(g_Kl + d) = make_uint2(l0, l1);
        sV[r][c4] = vv.x; sV[r][c4 + 1] = vv.y; sV[r][c4 + 2] = vv.z; sV[r][c4 + 3] = vv.w;
    }
    __syncthreads();
    #pragma unroll
    for (int it = 0; it < 4; it++) {
        int idx = it * 256 + tid;
        int d = idx >> 4, s4 = (idx & 15) << 2;
        float x0 = sV[s4][d], x1 = sV[s4 + 1][d], x2 = sV[s4 + 2][d], x3 = sV[s4 + 3][d];
        uint32_t h0, l0, h1, l1;
        split_pack(x0, x1, h0, l0);
        split_pack(x2, x3, h1, l1);
        size_t dst = ((size_t)bh * DKH + d) * SEQ + st * 64 + s4;
        *reinterpret_cast<uint2*>(g_Vh + dst) = make_uint2(h0, h1);
        *reinterpret_cast<uint2*>(g_Vl + dst) = make_uint2(l0, l1);
    }
}

__global__ void __launch_bounds__(256) convert_w(const float* __restrict__ Wo) {
    int idx = blockIdx.x * 256 + threadIdx.x;
    size_t e = (size_t)idx * 4;
    float4 w = *reinterpret_cast<const float4*>(Wo + e);
    uint32_t h0, l0, h1, l1;
    split_pack(w.x, w.y, h0, l0);
    split_pack(w.z, w.w, h1, l1);
    *reinterpret_cast<uint2*>(g_Wh + e) = make_uint2(h0, h1);
    *reinterpret_cast<uint2*>(g_Wl + e) = make_uint2(l0, l1);
}

// ---------------------------------------------------------------------------
// Attention: CTA = 128 queries x one head, 256 threads.
// 3-stage cp.async pipeline, ONE __syncthreads per tile, softmax interleaved
// with PV per 16-column chunk so scalar work hides under tensor work.
// ---------------------------------------------------------------------------
#define LDA 72
#define PLANE (64 * LDA)
#define STAGE (4 * PLANE)              // Kh,Kl,Vh,Vl (elems)
#define NSTG  3
#define ATTN_SMEM (NSTG * STAGE * 2)   // 110592 B

__global__ void __launch_bounds__(256, 2) attn_kernel(const float* __restrict__ Qg,
                                                      const float* __restrict__ AWg) {
    extern __shared__ __nv_bfloat16 sm[];
    const uint32_t smbase = (uint32_t)__cvta_generic_to_shared(sm);

    const int qt = blockIdx.x, h = blockIdx.y, b = blockIdx.z;
    const int tid = threadIdx.x;
    const int warp = tid >> 5, lane = tid & 31;
    const int g = lane >> 2, tq = lane & 3;
    const int q0 = qt * 128;
    const int bh = b * NH + h;

    // ldmatrix per-thread row offset for B-fragments ([n][k] tiles)
    const int browoff = (((lane >> 4) << 3) + (lane & 7)) * LDA + (((lane >> 3) & 1) << 3);

    const size_t kplane = (size_t)bh * SEQ * DKH;
    const __nv_bfloat16* gKh = g_Kh + kplane;
    const __nv_bfloat16* gKl = g_Kl + kplane;
    const __nv_bfloat16* gVh = g_Vh + kplane;
    const __nv_bfloat16* gVl = g_Vl + kplane;

    auto stage_load = [&](int st, int sb) {
        const size_t ko = (size_t)st * 64 * DKH;
        const int vo = st * 64;
        #pragma unroll
        for (int i = 0; i < 8; i++) {
            int id = tid + i * 256;
            int plane = id >> 9, rem = id & 511;
            int r = rem >> 3, c = rem & 7;
            const __nv_bfloat16* src;
            if (plane == 0)      src = gKh + ko + (size_t)r * DKH + c * 8;
            else if (plane == 1) src = gKl + ko + (size_t)r * DKH + c * 8;
            else if (plane == 2) src = gVh + (size_t)r * SEQ + vo + c * 8;
            else                 src = gVl + (size_t)r * SEQ + vo + c * 8;
            cp16(smbase + (sb * STAGE + plane * PLANE + r * LDA + c * 8) * 2, src);
        }
        CP_COMMIT();
    };

    stage_load(0, 0);
    stage_load(1, 1);

    // ---- Q fragments straight from gmem (one-time) ----
    uint32_t qah[4][4], qal[4][4];
    {
        const float* Q0 = Qg + ((size_t)b * NQ + q0 + warp * 16 + g) * DM + h * DKH;
        const float* Q1 = Q0 + (size_t)8 * DM;
        #pragma unroll
        for (int kt = 0; kt < 4; kt++) {
            int c0 = kt * 16 + tq * 2;
            float2 x0 = *reinterpret_cast<const float2*>(Q0 + c0);
            float2 x1 = *reinterpret_cast<const float2*>(Q1 + c0);
            float2 x2 = *reinterpret_cast<const float2*>(Q0 + c0 + 8);
            float2 x3 = *reinterpret_cast<const float2*>(Q1 + c0 + 8);
            split_pack(x0.x, x0.y, qah[kt][0], qal[kt][0]);
            split_pack(x1.x, x1.y, qah[kt][1], qal[kt][1]);
            split_pack(x2.x, x2.y, qah[kt][2], qal[kt][2]);
            split_pack(x3.x, x3.y, qah[kt][3], qal[kt][3]);
        }
    }

    const float* Wr0 = AWg + ((size_t)bh * NQ + q0 + warp * 16 + g) * SEQ + tq * 2;
    const float* Wr1 = Wr0 + (size_t)8 * SEQ;

    float acc[8][4];
    #pragma unroll
    for (int j = 0; j < 8; j++) { acc[j][0] = acc[j][1] = acc[j][2] = acc[j][3] = 0.f; }
    float L0 = 0.f, L1 = 0.f;

    for (int st = 0; st < SEQ / 64; st++) {
        // wait for tile st's stage, then (after barrier) prefetch st+2
        if (st < SEQ / 64 - 1) { CP_WAIT(1); } else { CP_WAIT(0); }
        __syncthreads();
        if (st + 2 < SEQ / 64) stage_load(st + 2, (st + 2) % NSTG);

        const int buf = st % NSTG;
        const uint32_t sKh = smbase + (buf * STAGE) * 2;
        const uint32_t sVh = sKh + (2 * PLANE) * 2;

        // prefetch W chunk 0 (latency hidden under QK MMAs)
        float2 wbuf[2][4];
        {
            const float* Wc0 = Wr0 + st * 64;
            const float* Wc1 = Wr1 + st * 64;
            wbuf[0][0] = __ldg(reinterpret_cast<const float2*>(Wc0));
            wbuf[0][1] = __ldg(reinterpret_cast<const float2*>(Wc0 + 8));
            wbuf[0][2] = __ldg(reinterpret_cast<const float2*>(Wc1));
            wbuf[0][3] = __ldg(reinterpret_cast<const float2*>(Wc1 + 8));
        }

        // ---- QK^T (3-pass hi/lo split), ldmatrix fragments ----
        float sc[8][4];
        #pragma unroll
        for (int j = 0; j < 8; j++) { sc[j][0] = sc[j][1] = sc[j][2] = sc[j][3] = 0.f; }
        #pragma unroll
        for (int kt = 0; kt < 4; kt++) {
            #pragma unroll
            for (int jp = 0; jp < 4; jp++) {
                uint32_t a = sKh + (jp * 16 * LDA + browoff + kt * 16) * 2;
                uint32_t h0, h1, h2, h3, l0, l1, l2, l3;
                ldsm_x4(h0, h1, h2, h3, a);
                ldsm_x4(l0, l1, l2, l3, a + PLANE * 2);
                mma_bf16(sc[2 * jp],     qah[kt], h0, h1);
                mma_bf16(sc[2 * jp],     qah[kt], l0, l1);
                mma_bf16(sc[2 * jp],     qal[kt], h0, h1);
                mma_bf16(sc[2 * jp + 1], qah[kt], h2, h3);
                mma_bf16(sc[2 * jp + 1], qah[kt], l2, l3);
                mma_bf16(sc[2 * jp + 1], qal[kt], h2, h3);
            }
        }

        // ---- interleaved softmax + PV, 16-column chunks ----
        float rs0 = 0.f, rs1 = 0.f;
        #pragma unroll
        for (int kt = 0; kt < 4; kt++) {
            // prefetch W chunk kt+1 (hidden under this chunk's PV MMAs)
            if (kt < 3) {
                const float* Wc0 = Wr0 + st * 64 + (2 * (kt + 1)) * 8;
                const float* Wc1 = Wr1 + st * 64 + (2 * (kt + 1)) * 8;
                wbuf[(kt + 1) & 1][0] = __ldg(reinterpret_cast<const float2*>(Wc0));
                wbuf[(kt + 1) & 1][1] = __ldg(reinterpret_cast<const float2*>(Wc0 + 8));
                wbuf[(kt + 1) & 1][2] = __ldg(reinterpret_cast<const float2*>(Wc1));
                wbuf[(kt + 1) & 1][3] = __ldg(reinterpret_cast<const float2*>(Wc1 + 8));
            }

            const int j0 = 2 * kt, j1 = j0 + 1;
            const float2 wa = wbuf[kt & 1][0], wb = wbuf[kt & 1][1];
            const float2 wc = wbuf[kt & 1][2], wd = wbuf[kt & 1][3];
            float p00 = ex2f(sc[j0][0] * CSLOG2E * wa.x);
            float p01 = ex2f(sc[j0][1] * CSLOG2E * wa.y);
            float p10 = ex2f(sc[j0][2] * CSLOG2E * wc.x);
            float p11 = ex2f(sc[j0][3] * CSLOG2E * wc.y);
            float q00 = ex2f(sc[j1][0] * CSLOG2E * wb.x);
            float q01 = ex2f(sc[j1][1] * CSLOG2E * wb.y);
            float q10 = ex2f(sc[j1][2] * CSLOG2E * wd.x);
            float q11 = ex2f(sc[j1][3] * CSLOG2E * wd.y);
            rs0 += p00 + p01 + q00 + q01;
            rs1 += p10 + p11 + q10 + q11;

            uint32_t pah[4], pal[4];
            split_pack(p00, p01, pah[0], pal[0]);
            split_pack(p10, p11, pah[1], pal[1]);
            split_pack(q00, q01, pah[2], pal[2]);
            split_pack(q10, q11, pah[3], pal[3]);

            #pragma unroll
            for (int jp = 0; jp < 4; jp++) {
                uint32_t a = sVh + (jp * 16 * LDA + browoff + kt * 16) * 2;
                uint32_t h0, h1, h2, h3, l0, l1, l2, l3;
                ldsm_x4(h0, h1, h2, h3, a);
                ldsm_x4(l0, l1, l2, l3, a + PLANE * 2);
                mma_bf16(acc[2 * jp],     pah, h0, h1);
                mma_bf16(acc[2 * jp],     pah, l0, l1);
                mma_bf16(acc[2 * jp],     pal, h0, h1);
                mma_bf16(acc[2 * jp + 1], pah, h2, h3);
                mma_bf16(acc[2 * jp + 1], pah, l2, l3);
                mma_bf16(acc[2 * jp + 1], pal, h2, h3);
            }
        }

        rs0 += __shfl_xor_sync(0xffffffffu, rs0, 1);
        rs0 += __shfl_xor_sync(0xffffffffu, rs0, 2);
        rs1 += __shfl_xor_sync(0xffffffffu, rs1, 1);
        rs1 += __shfl_xor_sync(0xffffffffu, rs1, 2);
        L0 += rs0;
        L1 += rs1;
    }

    // ---- epilogue: normalize, split to bf16 hi/lo ctx planes ----
    float inv0 = 1.f / L0, inv1 = 1.f / L1;
    size_t C0 = ((size_t)b * NQ + q0 + warp * 16 + g) * DM + h * DKH;
    size_t C1 = C0 + (size_t)8 * DM;
    #pragma unroll
    for (int j = 0; j < 8; j++) {
        int c = j * 8 + tq * 2;
        uint32_t h0, l0, h1, l1;
        split_pack(acc[j][0] * inv0, acc[j][1] * inv0, h0, l0);
        split_pack(acc[j][2] * inv1, acc[j][3] * inv1, h1, l1);
        *reinterpret_cast<uint32_t*>(g_Ch + C0 + c) = h0;
        *reinterpret_cast<uint32_t*>(g_Cl + C0 + c) = l0;
        *reinterpret_cast<uint32_t*>(g_Ch + C1 + c) = h1;
        *reinterpret_cast<uint32_t*>(g_Cl + C1 + c) = l1;
    }
}

// ---------------------------------------------------------------------------
// Projection: out = ctx @ W^T + b. 128m x 64n, k-chunk 32, 3-stage cp.async
// pipeline with ONE __syncthreads per iteration, ldmatrix fragments.
// ---------------------------------------------------------------------------
#define LDK 40
#define PA  (128 * LDK)
#define PB  (64 * LDK)
#define PSTAGE (2 * PA + 2 * PB)       // elems per stage
#define PNSTG 3
#define PROJ_SMEM (PNSTG * PSTAGE * 2) // 92160 B

__global__ void __launch_bounds__(256) proj_kernel(const float* __restrict__ bo,
                                                   float* __restrict__ out) {
    extern __shared__ __nv_bfloat16 sm[];
    const uint32_t smbase = (uint32_t)__cvta_generic_to_shared(sm);

    const int n0 = blockIdx.x * 64;
    const int m0 = blockIdx.y * 128;
    const int tid = threadIdx.x;
    const int warp = tid >> 5, lane = tid & 31;
    const int g = lane >> 2, tq = lane & 3;

    const int browoff = (((lane >> 4) << 3) + (lane & 7)) * LDK + (((lane >> 3) & 1) << 3);
    const int arowoff = ((((lane >> 3) & 1) << 3) + (lane & 7)) * LDK + ((lane >> 4) << 3);

    float acc[8][4];
    #pragma unroll
    for (int j = 0; j < 8; j++) { acc[j][0] = acc[j][1] = acc[j][2] = acc[j][3] = 0.f; }

    auto load_stage = [&](int kc, int buf) {
        const int k0 = kc * 32;
        #pragma unroll
        for (int i = 0; i < 6; i++) {
            int id = tid + i * 256;
            const __nv_bfloat16* src;
            uint32_t dst;
            if (id < 1024) {
                int plane = id >> 9, rem = id & 511;
                int r = rem >> 2, c = rem & 3;
                const __nv_bfloat16* gp = plane ? g_Cl : g_Ch;
                src = gp + (size_t)(m0 + r) * DM + k0 + c * 8;
                dst = smbase + (buf * PSTAGE + plane * PA + r * LDK + c * 8) * 2;
            } else {
                int id2 = id - 1024;
                int plane = id2 >> 8, rem = id2 & 255;
                int r = rem >> 2, c = rem & 3;
                const __nv_bfloat16* gp = plane ? g_Wl : g_Wh;
                src = gp + (size_t)(n0 + r) * DM + k0 + c * 8;
                dst = smbase + (buf * PSTAGE + 2 * PA + plane * PB + r * LDK + c * 8) * 2;
            }
            cp16(dst, src);
        }
        CP_COMMIT();
    };

    load_stage(0, 0);
    load_stage(1, 1);

    const int NK = DM / 32;
    for (int kc = 0; kc < NK; kc++) {
        if (kc < NK - 1) { CP_WAIT(1); } else { CP_WAIT(0); }
        __syncthreads();
        if (kc + 2 < NK) load_stage(kc + 2, (kc + 2) % PNSTG);

        const int buf = kc % PNSTG;
        const uint32_t sA = smbase + (buf * PSTAGE) * 2;
        const uint32_t sB = sA + (2 * PA) * 2;

        uint32_t ah[2][4], al[2][4];
        #pragma unroll
        for (int kt = 0; kt < 2; kt++) {
            uint32_t a = sA + (warp * 16 * LDK + arowoff + kt * 16) * 2;
            ldsm_x4(ah[kt][0], ah[kt][1], ah[kt][2], ah[kt][3], a);
            ldsm_x4(al[kt][0], al[kt][1], al[kt][2], al[kt][3], a + PA * 2);
        }
        #pragma unroll
        for (int kt = 0; kt < 2; kt++) {
            #pragma unroll
            for (int jp = 0; jp < 4; jp++) {
                uint32_t a = sB + (jp * 16 * LDK + browoff + kt * 16) * 2;
                uint32_t h0, h1, h2, h3, l0, l1, l2, l3;
                ldsm_x4(h0, h1, h2, h3, a);
                ldsm_x4(l0, l1, l2, l3, a + PB * 2);
                mma_bf16(acc[2 * jp],     ah[kt], h0, h1);
                mma_bf16(acc[2 * jp],     ah[kt], l0, l1);
                mma_bf16(acc[2 * jp],     al[kt], h0, h1);
                mma_bf16(acc[2 * jp + 1], ah[kt], h2, h3);
                mma_bf16(acc[2 * jp + 1], ah[kt], l2, l3);
                mma_bf16(acc[2 * jp + 1], al[kt], h2, h3);
            }
        }
    }

    int r0 = m0 + warp * 16 + g, r1 = r0 + 8;
    #pragma unroll
    for (int j = 0; j < 8; j++) {
        int c = n0 + j * 8 + tq * 2;
        float2 bb = *reinterpret_cast<const float2*>(bo + c);
        float2 o0 = make_float2(acc[j][0] + bb.x, acc[j][1] + bb.y);
        float2 o1 = make_float2(acc[j][2] + bb.x, acc[j][3] + bb.y);
        *reinterpret_cast<float2*>(out + (size_t)r0 * DM + c) = o0;
        *reinterpret_cast<float2*>(out + (size_t)r1 * DM + c) = o1;
    }
}

// ---------------------------------------------------------------------------
extern "C" void kernel_launch(void* const* d_in, const int* in_sizes, int n_in,
                              void* d_out, int out_size) {
    const float* Q  = (const float*)d_in[0];
    const float* K  = (const float*)d_in[1];
    const float* V  = (const float*)d_in[2];
    const float* AW = (const float*)d_in[3];
    const float* Wo = (const float*)d_in[4];
    const float* bo = (const float*)d_in[5];
    float* out = (float*)d_out;

    cudaFuncSetAttribute(attn_kernel, cudaFuncAttributeMaxDynamicSharedMemorySize, ATTN_SMEM);
    cudaFuncSetAttribute(proj_kernel, cudaFuncAttributeMaxDynamicSharedMemorySize, PROJ_SMEM);

    convert_kv<<<dim3(SEQ / 64, NH, BATCH), 256>>>(K, V);
    convert_w<<<DM * DM / 1024, 256>>>(Wo);
    attn_kernel<<<dim3(NQ / 128, NH, BATCH), 256, ATTN_SMEM>>>(Q, AW);
    proj_kernel<<<dim3(DM / 64, BATCH * NQ / 128), 256, PROJ_SMEM>>>(bo, out);
}